// round 4
// baseline (speedup 1.0000x reference)
#include <cuda_runtime.h>
#include <cstdint>

// CapsuleLayer dynamic routing — cp.async double-buffered w staging.
// x: [B=256, N=1152, CI=8] f32, w: [C=10, N=1152, CI=8, CO=16] f32
// out: [C, B, 1, 1, 16] f32
//
// One CTA = (c, pair of b). 576 threads; g = tid&1 (which b), r = tid>>1.
// w[c] is streamed in 8 blocks of 144 rows via cp.async.cg (L1 bypass) into
// two ping-pong SMEM buffers; block s+2 is prefetched while the owning warp
// half computes block s. Each thread owns 4 route nodes (n = r + 288k);
// their 4x16 prior vectors stay in registers through all 3 routing
// iterations (phase 2 = shuffles + tiny SMEM reductions).

#define Cc 10
#define Bb 256
#define Nn 1152
#define NTHREADS 576
#define NWARPS 18
#define NBLKS 8
#define RPB 144                 // rows per block
#define STR 33                  // float4 stride of a padded row
#define BUF_F4 (RPB * STR)      // 4752 float4 per buffer
#define F4_PB (RPB * 32)        // 4608 float4 staged per block
#define CPT (F4_PB / NTHREADS)  // 8 cp.async per thread per block

#define SMEM_BYTES (2*BUF_F4*16 + (NWARPS*2*16 + NWARPS*2 + 2*16)*4)

__device__ __forceinline__ void cp_async16(uint32_t dst, const void* src) {
    asm volatile("cp.async.cg.shared.global [%0], [%1], 16;\n"
                 :: "r"(dst), "l"(src));
}
__device__ __forceinline__ void cp_commit() {
    asm volatile("cp.async.commit_group;\n");
}
template <int N>
__device__ __forceinline__ void cp_wait() {
    asm volatile("cp.async.wait_group %0;\n" :: "n"(N));
}

__global__ __launch_bounds__(NTHREADS, 1)
void capsule_kernel(const float* __restrict__ x,
                    const float* __restrict__ w,
                    float* __restrict__ out)
{
    extern __shared__ float4 smem4[];
    float4* buf[2] = { smem4, smem4 + BUF_F4 };
    float*  wred = (float*)(smem4 + 2*BUF_F4);   // [18][2][16]
    float*  sred = wred + NWARPS*2*16;           // [18][2]
    float*  outv = sred + NWARPS*2;              // [2][16]

    const int tid  = threadIdx.x;
    const int g    = tid & 1;
    const int r    = tid >> 1;              // 0..287
    const int lane = tid & 31;
    const int wid  = tid >> 5;              // 0..17
    const int c    = blockIdx.x >> 7;
    const int bbase = (blockIdx.x & 127) << 1;
    const int b    = bbase + g;

    const float4* __restrict__ wsrc = (const float4*)(w + ((size_t)c * Nn) * 128);
    const uint32_t sbase = (uint32_t)__cvta_generic_to_shared(smem4);

    // per-block stage: 4608 float4 with 576 threads, padded-row layout
    auto stage = [&](int s) {
        const uint32_t dstb = sbase + (uint32_t)((s & 1) * (BUF_F4 * 16));
        const float4* src = wsrc + (size_t)s * F4_PB;
        #pragma unroll
        for (int j = 0; j < CPT; ++j) {
            const int m = tid + j * NTHREADS;
            const int row = m >> 5, q = m & 31;
            cp_async16(dstb + (uint32_t)(row * STR + q) * 16, src + m);
        }
        cp_commit();
    };

    // ================= Phase 1: priors -> registers =================
    stage(0);
    stage(1);

    const int hi   = (r >= RPB) ? 1 : 0;    // warp-uniform
    const int rloc = r - hi * RPB;          // row within block
    float P[4][16];

    #pragma unroll
    for (int s = 0; s < NBLKS; ++s) {
        if (s < NBLKS - 2) cp_wait<1>(); else cp_wait<0>();
        __syncthreads();                     // block s resident in buf[s&1]

        if ((s & 1) == hi) {
            const int k = s >> 1;
            const int n = s * RPB + rloc;    // == r + 288k
            const float* xp = x + ((size_t)b * Nn + n) * 8;
            const float4 xa = *(const float4*)xp;
            const float4 xb = *(const float4*)(xp + 4);
            const float xv[8] = {xa.x, xa.y, xa.z, xa.w, xb.x, xb.y, xb.z, xb.w};

            #pragma unroll
            for (int o = 0; o < 16; ++o) P[k][o] = 0.f;

            const float4* wr = buf[s & 1] + rloc * STR;
            #pragma unroll
            for (int i = 0; i < 8; ++i) {
                const float xvi = xv[i];
                #pragma unroll
                for (int m = 0; m < 4; ++m) {
                    const float4 wv = wr[i * 4 + m];
                    P[k][4*m+0] = fmaf(xvi, wv.x, P[k][4*m+0]);
                    P[k][4*m+1] = fmaf(xvi, wv.y, P[k][4*m+1]);
                    P[k][4*m+2] = fmaf(xvi, wv.z, P[k][4*m+2]);
                    P[k][4*m+3] = fmaf(xvi, wv.w, P[k][4*m+3]);
                }
            }
        }
        __syncthreads();                     // everyone done with buf[s&1]
        if (s + 2 < NBLKS) stage(s + 2);
    }

    // ================= Phase 2: routing =================
    // warp reductions over same-g lanes: shfl_xor offsets 2,4,8,16
    float Lr[4];

    // ---- iteration 0: s = mean_n priors ----
    {
        float acc[16];
        #pragma unroll
        for (int o = 0; o < 16; ++o)
            acc[o] = P[0][o] + P[1][o] + P[2][o] + P[3][o];
        #pragma unroll
        for (int off = 2; off <= 16; off <<= 1)
            #pragma unroll
            for (int o = 0; o < 16; ++o)
                acc[o] += __shfl_xor_sync(0xffffffffu, acc[o], off);
        if (lane < 2) {
            #pragma unroll
            for (int o = 0; o < 16; ++o)
                wred[(wid * 2 + g) * 16 + o] = acc[o];
        }
        __syncthreads();
        if (tid < 32) {
            const int g2 = tid & 1, o2 = tid >> 1;
            float sv = 0.f;
            #pragma unroll
            for (int wi = 0; wi < NWARPS; ++wi)
                sv += wred[(wi * 2 + g2) * 16 + o2];
            sv *= (1.0f / Nn);
            float sq = sv * sv;
            #pragma unroll
            for (int off = 2; off <= 16; off <<= 1)
                sq += __shfl_xor_sync(0xffffffffu, sq, off);
            const float coef = sq / (1.f + sq) * rsqrtf(sq);
            outv[g2 * 16 + o2] = sv * coef;
        }
        __syncthreads();
    }

    // ---- iterations 1 and 2 ----
    #pragma unroll
    for (int it = 1; it < 3; ++it) {
        float ovr[16];
        #pragma unroll
        for (int o = 0; o < 16; ++o) ovr[o] = outv[g * 16 + o];

        // logits + max
        float lmax = -1e30f;
        #pragma unroll
        for (int k = 0; k < 4; ++k) {
            float dot = 0.f;
            #pragma unroll
            for (int o = 0; o < 16; ++o) dot = fmaf(P[k][o], ovr[o], dot);
            const float L = (it == 1) ? dot : (Lr[k] + dot);
            Lr[k] = L;
            lmax = fmaxf(lmax, L);
        }
        #pragma unroll
        for (int off = 2; off <= 16; off <<= 1)
            lmax = fmaxf(lmax, __shfl_xor_sync(0xffffffffu, lmax, off));
        __syncthreads();                 // previous sred consumers done
        if (lane < 2) sred[wid * 2 + g] = lmax;
        __syncthreads();
        float M = -1e30f;
        #pragma unroll
        for (int wi = 0; wi < NWARPS; ++wi)
            M = fmaxf(M, sred[wi * 2 + g]);

        // exp + Z
        float e[4], lsum = 0.f;
        #pragma unroll
        for (int k = 0; k < 4; ++k) {
            e[k] = __expf(Lr[k] - M);
            lsum += e[k];
        }
        #pragma unroll
        for (int off = 2; off <= 16; off <<= 1)
            lsum += __shfl_xor_sync(0xffffffffu, lsum, off);
        __syncthreads();                 // all M reads done
        if (lane < 2) sred[wid * 2 + g] = lsum;
        __syncthreads();
        float Z = 0.f;
        #pragma unroll
        for (int wi = 0; wi < NWARPS; ++wi)
            Z += sred[wi * 2 + g];

        // s[o] = (1/Z) * sum_n e[n] * P[n][o]
        float acc[16];
        #pragma unroll
        for (int o = 0; o < 16; ++o)
            acc[o] = fmaf(e[0], P[0][o],
                     fmaf(e[1], P[1][o],
                     fmaf(e[2], P[2][o], e[3] * P[3][o])));
        #pragma unroll
        for (int off = 2; off <= 16; off <<= 1)
            #pragma unroll
            for (int o = 0; o < 16; ++o)
                acc[o] += __shfl_xor_sync(0xffffffffu, acc[o], off);
        if (lane < 2) {
            #pragma unroll
            for (int o = 0; o < 16; ++o)
                wred[(wid * 2 + g) * 16 + o] = acc[o];
        }
        __syncthreads();
        if (tid < 32) {
            const int g2 = tid & 1, o2 = tid >> 1;
            float sv = 0.f;
            #pragma unroll
            for (int wi = 0; wi < NWARPS; ++wi)
                sv += wred[(wi * 2 + g2) * 16 + o2];
            sv /= Z;
            float sq = sv * sv;
            #pragma unroll
            for (int off = 2; off <= 16; off <<= 1)
                sq += __shfl_xor_sync(0xffffffffu, sq, off);
            const float coef = sq / (1.f + sq) * rsqrtf(sq);
            outv[g2 * 16 + o2] = sv * coef;
        }
        __syncthreads();
    }

    // ================= output: [C, B, 1, 1, 16] =================
    if (tid < 32) {
        const int g2 = tid & 1, o2 = tid >> 1;
        out[((size_t)c * Bb + bbase + g2) * 16 + o2] = outv[g2 * 16 + o2];
    }
}

extern "C" void kernel_launch(void* const* d_in, const int* in_sizes, int n_in,
                              void* d_out, int out_size)
{
    const float* x = (const float*)d_in[0];
    const float* w = (const float*)d_in[1];
    float* out = (float*)d_out;

    cudaFuncSetAttribute(capsule_kernel,
                         cudaFuncAttributeMaxDynamicSharedMemorySize, SMEM_BYTES);

    const int grid = Cc * (Bb / 2);   // 1280 CTAs
    capsule_kernel<<<grid, NTHREADS, SMEM_BYTES>>>(x, w, out);
}

// round 5
// speedup vs baseline: 1.0311x; 1.0311x over previous
#include <cuda_runtime.h>
#include <cstdint>

// CapsuleLayer dynamic routing — cp.async double-buffered w staging,
// all-thread compute via CO-split.
// x: [B=256, N=1152, CI=8] f32, w: [C=10, N=1152, CI=8, CO=16] f32
// out: [C, B, 1, 1, 16] f32
//
// One CTA = (c, pair of b). 576 threads; g = tid&1 (which b),
// oh = (tid>>1)&1 (which half of CO), row = tid>>2 (0..143).
// w[c] streams in 8 blocks of 144 rows via cp.async.cg into two ping-pong
// SMEM buffers; block s+2 prefetched while ALL threads compute block s.
// Each thread holds P[8][8] (its 8 route nodes x its 8 outputs) in registers
// through all 3 routing iterations.

#define Cc 10
#define Bb 256
#define Nn 1152
#define NTHREADS 576
#define NWARPS 18
#define NBLKS 8
#define RPB 144                 // rows per block
#define STR 33                  // float4 stride of a padded row
#define BUF_F4 (RPB * STR)      // 4752 float4 per buffer
#define F4_PB (RPB * 32)        // 4608 float4 staged per block
#define CPT (F4_PB / NTHREADS)  // 8 cp.async per thread per block

#define SMEM_BYTES (2*BUF_F4*16 + (NWARPS*2*16 + NWARPS*2 + 2*16)*4)

__device__ __forceinline__ void cp_async16(uint32_t dst, const void* src) {
    asm volatile("cp.async.cg.shared.global [%0], [%1], 16;\n"
                 :: "r"(dst), "l"(src));
}
__device__ __forceinline__ void cp_commit() {
    asm volatile("cp.async.commit_group;\n");
}
template <int N>
__device__ __forceinline__ void cp_wait() {
    asm volatile("cp.async.wait_group %0;\n" :: "n"(N));
}

__global__ __launch_bounds__(NTHREADS, 1)
void capsule_kernel(const float* __restrict__ x,
                    const float* __restrict__ w,
                    float* __restrict__ out)
{
    extern __shared__ float4 smem4[];
    float4* buf[2] = { smem4, smem4 + BUF_F4 };
    float*  wred = (float*)(smem4 + 2*BUF_F4);   // [18][2][16]
    float*  sred = wred + NWARPS*2*16;           // [18][2]
    float*  outv = sred + NWARPS*2;              // [2][16]

    const int tid  = threadIdx.x;
    const int g    = tid & 1;               // which b of pair
    const int oh   = (tid >> 1) & 1;        // which CO half
    const int rw   = tid >> 2;              // 0..143, row within block
    const int lane = tid & 31;
    const int wid  = tid >> 5;              // 0..17
    const int c    = blockIdx.x >> 7;
    const int bbase = (blockIdx.x & 127) << 1;
    const int b    = bbase + g;

    const float4* __restrict__ wsrc = (const float4*)(w + ((size_t)c * Nn) * 128);
    const uint32_t sbase = (uint32_t)__cvta_generic_to_shared(smem4);

    auto stage = [&](int s) {
        const uint32_t dstb = sbase + (uint32_t)((s & 1) * (BUF_F4 * 16));
        const float4* src = wsrc + (size_t)s * F4_PB;
        #pragma unroll
        for (int j = 0; j < CPT; ++j) {
            const int m = tid + j * NTHREADS;
            const int row = m >> 5, q = m & 31;
            cp_async16(dstb + (uint32_t)(row * STR + q) * 16, src + m);
        }
        cp_commit();
    };

    // ================= Phase 1: priors -> registers =================
    stage(0);
    stage(1);

    float P[NBLKS][8];

    #pragma unroll
    for (int s = 0; s < NBLKS; ++s) {
        if (s < NBLKS - 2) cp_wait<1>(); else cp_wait<0>();
        __syncthreads();                     // block s resident in buf[s&1]

        const int n = s * RPB + rw;
        const float* xp = x + ((size_t)b * Nn + n) * 8;
        const float4 xa = *(const float4*)xp;
        const float4 xb = *(const float4*)(xp + 4);
        const float xv[8] = {xa.x, xa.y, xa.z, xa.w, xb.x, xb.y, xb.z, xb.w};

        #pragma unroll
        for (int o = 0; o < 8; ++o) P[s][o] = 0.f;

        const float4* wr = buf[s & 1] + rw * STR + oh * 2;
        #pragma unroll
        for (int i = 0; i < 8; ++i) {
            const float xvi = xv[i];
            const float4 w0 = wr[i * 4 + 0];
            const float4 w1 = wr[i * 4 + 1];
            P[s][0] = fmaf(xvi, w0.x, P[s][0]);
            P[s][1] = fmaf(xvi, w0.y, P[s][1]);
            P[s][2] = fmaf(xvi, w0.z, P[s][2]);
            P[s][3] = fmaf(xvi, w0.w, P[s][3]);
            P[s][4] = fmaf(xvi, w1.x, P[s][4]);
            P[s][5] = fmaf(xvi, w1.y, P[s][5]);
            P[s][6] = fmaf(xvi, w1.z, P[s][6]);
            P[s][7] = fmaf(xvi, w1.w, P[s][7]);
        }

        __syncthreads();                     // done reading buf[s&1]
        if (s + 2 < NBLKS) stage(s + 2);
    }

    // ================= Phase 2: routing =================
    // Within-warp row reduction: shfl_xor offsets 4,8,16 (preserve g, oh).
    // o-half join: shfl_xor offset 2 (preserve g).
    float Lr[NBLKS];

    // ---- iteration 0: s = mean_n priors ----
    {
        float acc[8];
        #pragma unroll
        for (int o = 0; o < 8; ++o) {
            float a = 0.f;
            #pragma unroll
            for (int k = 0; k < NBLKS; ++k) a += P[k][o];
            acc[o] = a;
        }
        #pragma unroll
        for (int off = 4; off <= 16; off <<= 1)
            #pragma unroll
            for (int o = 0; o < 8; ++o)
                acc[o] += __shfl_xor_sync(0xffffffffu, acc[o], off);
        if (lane < 4) {
            #pragma unroll
            for (int o = 0; o < 8; ++o)
                wred[(wid * 2 + g) * 16 + oh * 8 + o] = acc[o];
        }
        __syncthreads();
        if (tid < 32) {
            const int g2 = tid & 1, o2 = tid >> 1;
            float sv = 0.f;
            #pragma unroll
            for (int wi = 0; wi < NWARPS; ++wi)
                sv += wred[(wi * 2 + g2) * 16 + o2];
            sv *= (1.0f / Nn);
            float sq = sv * sv;
            #pragma unroll
            for (int off = 2; off <= 16; off <<= 1)
                sq += __shfl_xor_sync(0xffffffffu, sq, off);
            const float coef = sq / (1.f + sq) * rsqrtf(sq);
            outv[g2 * 16 + o2] = sv * coef;
        }
        __syncthreads();
    }

    // ---- iterations 1 and 2 ----
    #pragma unroll
    for (int it = 1; it < 3; ++it) {
        float ovr[8];
        #pragma unroll
        for (int o = 0; o < 8; ++o) ovr[o] = outv[g * 16 + oh * 8 + o];

        // logits + max (half-dot, join halves via shfl 2)
        float lmax = -1e30f;
        #pragma unroll
        for (int k = 0; k < NBLKS; ++k) {
            float dot = 0.f;
            #pragma unroll
            for (int o = 0; o < 8; ++o) dot = fmaf(P[k][o], ovr[o], dot);
            dot += __shfl_xor_sync(0xffffffffu, dot, 2);   // full 16-dot
            const float L = (it == 1) ? dot : (Lr[k] + dot);
            Lr[k] = L;
            lmax = fmaxf(lmax, L);
        }
        #pragma unroll
        for (int off = 4; off <= 16; off <<= 1)
            lmax = fmaxf(lmax, __shfl_xor_sync(0xffffffffu, lmax, off));
        __syncthreads();                 // previous sred consumers done
        if (lane < 2) sred[wid * 2 + g] = lmax;
        __syncthreads();
        float M = -1e30f;
        #pragma unroll
        for (int wi = 0; wi < NWARPS; ++wi)
            M = fmaxf(M, sred[wi * 2 + g]);

        // exp + Z (e identical across oh; reduce rows only)
        float e[NBLKS], lsum = 0.f;
        #pragma unroll
        for (int k = 0; k < NBLKS; ++k) {
            e[k] = __expf(Lr[k] - M);
            lsum += e[k];
        }
        #pragma unroll
        for (int off = 4; off <= 16; off <<= 1)
            lsum += __shfl_xor_sync(0xffffffffu, lsum, off);
        __syncthreads();                 // all M reads done
        if (lane < 2) sred[wid * 2 + g] = lsum;
        __syncthreads();
        float Z = 0.f;
        #pragma unroll
        for (int wi = 0; wi < NWARPS; ++wi)
            Z += sred[wi * 2 + g];

        // s[o] = (1/Z) * sum_n e[n] * P[n][o]
        float acc[8];
        #pragma unroll
        for (int o = 0; o < 8; ++o) {
            float a = 0.f;
            #pragma unroll
            for (int k = 0; k < NBLKS; ++k) a = fmaf(e[k], P[k][o], a);
            acc[o] = a;
        }
        #pragma unroll
        for (int off = 4; off <= 16; off <<= 1)
            #pragma unroll
            for (int o = 0; o < 8; ++o)
                acc[o] += __shfl_xor_sync(0xffffffffu, acc[o], off);
        if (lane < 4) {
            #pragma unroll
            for (int o = 0; o < 8; ++o)
                wred[(wid * 2 + g) * 16 + oh * 8 + o] = acc[o];
        }
        __syncthreads();
        if (tid < 32) {
            const int g2 = tid & 1, o2 = tid >> 1;
            float sv = 0.f;
            #pragma unroll
            for (int wi = 0; wi < NWARPS; ++wi)
                sv += wred[(wi * 2 + g2) * 16 + o2];
            sv /= Z;
            float sq = sv * sv;
            #pragma unroll
            for (int off = 2; off <= 16; off <<= 1)
                sq += __shfl_xor_sync(0xffffffffu, sq, off);
            const float coef = sq / (1.f + sq) * rsqrtf(sq);
            outv[g2 * 16 + o2] = sv * coef;
        }
        __syncthreads();
    }

    // ================= output: [C, B, 1, 1, 16] =================
    if (tid < 32) {
        const int g2 = tid & 1, o2 = tid >> 1;
        out[((size_t)c * Bb + bbase + g2) * 16 + o2] = outv[g2 * 16 + o2];
    }
}

extern "C" void kernel_launch(void* const* d_in, const int* in_sizes, int n_in,
                              void* d_out, int out_size)
{
    const float* x = (const float*)d_in[0];
    const float* w = (const float*)d_in[1];
    float* out = (float*)d_out;

    cudaFuncSetAttribute(capsule_kernel,
                         cudaFuncAttributeMaxDynamicSharedMemorySize, SMEM_BYTES);

    const int grid = Cc * (Bb / 2);   // 1280 CTAs
    capsule_kernel<<<grid, NTHREADS, SMEM_BYTES>>>(x, w, out);
}

// round 6
// speedup vs baseline: 1.4805x; 1.4358x over previous
#include <cuda_runtime.h>
#include <cuda.h>
#include <cstdint>

// CapsuleLayer dynamic routing — TMA (SW128) double-buffered w staging.
// x: [B=256, N=1152, CI=8] f32, w: [C=10, N=1152, CI=8, CO=16] f32
// out: [C, B, 1, 1, 16] f32
//
// One CTA = (c, pair of b). 576 threads; g=tid&1 (which b), oh=(tid>>1)&1
// (CO half), rw=tid>>2 (row 0..143). w[c] streams in 8 blocks of 144 rows;
// each block = 4 TMA 2D loads (box 32 floats x 144 rows, SW128 swizzle)
// into ping-pong SMEM buffers, signaled by mbarrier+expect_tx. LDS reads use
// the SW128 XOR -> 2 conflict-free phases. Each thread holds P[8][8] in
// registers through all 3 routing iterations.

#define Cc 10
#define Bb 256
#define Nn 1152
#define NTHREADS 576
#define NWARPS 18
#define NBLKS 8
#define RPB 144
#define COLW  18432              // bytes per 128B-column box (144*128)
#define BUFB  (4*COLW)           // 73728 bytes per buffer
#define MBAR_OFF (2*BUFB)        // 147456
#define WRED_OFF (MBAR_OFF + 16)
#define SRED_OFF (WRED_OFF + NWARPS*2*16*4)
#define OUTV_OFF (SRED_OFF + NWARPS*2*4)
#define SMEM_BYTES (OUTV_OFF + 2*16*4)

__device__ __forceinline__ void mbar_init(uint32_t a, uint32_t cnt) {
    asm volatile("mbarrier.init.shared.b64 [%0], %1;" :: "r"(a), "r"(cnt) : "memory");
}
__device__ __forceinline__ void mbar_expect_tx(uint32_t a, uint32_t bytes) {
    asm volatile("mbarrier.arrive.expect_tx.shared.b64 _, [%0], %1;"
                 :: "r"(a), "r"(bytes) : "memory");
}
__device__ __forceinline__ void mbar_wait(uint32_t a, uint32_t parity) {
    asm volatile(
        "{\n\t.reg .pred P1;\n\t"
        "W_%=:\n\t"
        "mbarrier.try_wait.parity.acquire.cta.shared::cta.b64 P1, [%0], %1, 0x989680;\n\t"
        "@P1 bra.uni D_%=;\n\t"
        "bra.uni W_%=;\n\t"
        "D_%=:\n\t}"
        :: "r"(a), "r"(parity) : "memory");
}
__device__ __forceinline__ void tma2d(uint32_t dst, const CUtensorMap* m,
                                      int cx, int cy, uint32_t mb) {
    asm volatile(
        "cp.async.bulk.tensor.2d.shared::cta.global.tile.mbarrier::complete_tx::bytes "
        "[%0], [%1, {%2, %3}], [%4];"
        :: "r"(dst), "l"(m), "r"(cx), "r"(cy), "r"(mb) : "memory");
}

__global__ __launch_bounds__(NTHREADS, 1)
void capsule_kernel(const __grid_constant__ CUtensorMap tmap,
                    const float* __restrict__ x,
                    float* __restrict__ out)
{
    extern __shared__ char smc[];
    float* wred = (float*)(smc + WRED_OFF);    // [18][2][16]
    float* sred = (float*)(smc + SRED_OFF);    // [18][2]
    float* outv = (float*)(smc + OUTV_OFF);    // [2][16]

    const int tid  = threadIdx.x;
    const int g    = tid & 1;
    const int oh   = (tid >> 1) & 1;
    const int rw   = tid >> 2;              // 0..143
    const int lane = tid & 31;
    const int wid  = tid >> 5;
    const int c    = blockIdx.x >> 7;
    const int bbase = (blockIdx.x & 127) << 1;
    const int b    = bbase + g;

    const uint32_t sbase = (uint32_t)__cvta_generic_to_shared(smc);
    const uint32_t mbar[2] = { sbase + MBAR_OFF, sbase + MBAR_OFF + 8 };

    auto stage = [&](int s) {                 // tid 0 only
        const uint32_t dstb = sbase + (s & 1) * BUFB;
        const int cy = c * Nn + s * RPB;
        mbar_expect_tx(mbar[s & 1], BUFB);
        #pragma unroll
        for (int j = 0; j < 4; ++j)
            tma2d(dstb + j * COLW, &tmap, j * 32, cy, mbar[s & 1]);
    };

    if (tid == 0) { mbar_init(mbar[0], 1); mbar_init(mbar[1], 1); }
    __syncthreads();
    if (tid == 0) { stage(0); stage(1); }

    // ================= Phase 1: priors -> registers =================
    float P[NBLKS][8];
    const int r7  = rw & 7;
    const int oh2 = oh * 2;
    const uint32_t rowoff = (uint32_t)rw * 128;

    #pragma unroll
    for (int s = 0; s < NBLKS; ++s) {
        mbar_wait(mbar[s & 1], (s >> 1) & 1);   // block s resident

        const int n = s * RPB + rw;
        const float* xp = x + ((size_t)b * Nn + n) * 8;
        const float4 xa = *(const float4*)xp;
        const float4 xb = *(const float4*)(xp + 4);
        const float xv[8] = {xa.x, xa.y, xa.z, xa.w, xb.x, xb.y, xb.z, xb.w};

        #pragma unroll
        for (int o = 0; o < 8; ++o) P[s][o] = 0.f;

        const char* bufp = smc + (size_t)((s & 1) * BUFB) + rowoff;
        #pragma unroll
        for (int i = 0; i < 8; ++i) {
            const float xvi = xv[i];
            #pragma unroll
            for (int m = 0; m < 2; ++m) {
                const int C = i * 4 + m;                 // 16B unit (oh=0 base)
                const uint32_t u = (uint32_t)((C & 7) + oh2);
                const uint32_t off = (uint32_t)((C >> 3) * COLW)
                                   + (((u ^ (uint32_t)r7)) << 4);
                const float4 wv = *(const float4*)(bufp + off);
                P[s][m*4+0] = fmaf(xvi, wv.x, P[s][m*4+0]);
                P[s][m*4+1] = fmaf(xvi, wv.y, P[s][m*4+1]);
                P[s][m*4+2] = fmaf(xvi, wv.z, P[s][m*4+2]);
                P[s][m*4+3] = fmaf(xvi, wv.w, P[s][m*4+3]);
            }
        }

        __syncthreads();                      // all done reading buf[s&1]
        if (s + 2 < NBLKS && tid == 0) stage(s + 2);
    }

    // ================= Phase 2: routing =================
    // Row reduction within warp: shfl_xor 4,8,16 (preserve g,oh).
    // o-half join: shfl_xor 2 (preserve g).
    float Lr[NBLKS];

    // ---- iteration 0: s = mean_n priors ----
    {
        float acc[8];
        #pragma unroll
        for (int o = 0; o < 8; ++o) {
            float a = 0.f;
            #pragma unroll
            for (int k = 0; k < NBLKS; ++k) a += P[k][o];
            acc[o] = a;
        }
        #pragma unroll
        for (int off = 4; off <= 16; off <<= 1)
            #pragma unroll
            for (int o = 0; o < 8; ++o)
                acc[o] += __shfl_xor_sync(0xffffffffu, acc[o], off);
        if (lane < 4) {
            #pragma unroll
            for (int o = 0; o < 8; ++o)
                wred[(wid * 2 + g) * 16 + oh * 8 + o] = acc[o];
        }
        __syncthreads();
        if (tid < 32) {
            const int g2 = tid & 1, o2 = tid >> 1;
            float sv = 0.f;
            #pragma unroll
            for (int wi = 0; wi < NWARPS; ++wi)
                sv += wred[(wi * 2 + g2) * 16 + o2];
            sv *= (1.0f / Nn);
            float sq = sv * sv;
            #pragma unroll
            for (int off = 2; off <= 16; off <<= 1)
                sq += __shfl_xor_sync(0xffffffffu, sq, off);
            const float coef = sq / (1.f + sq) * rsqrtf(sq);
            outv[g2 * 16 + o2] = sv * coef;
        }
        __syncthreads();
    }

    // ---- iterations 1 and 2 ----
    #pragma unroll
    for (int it = 1; it < 3; ++it) {
        float ovr[8];
        #pragma unroll
        for (int o = 0; o < 8; ++o) ovr[o] = outv[g * 16 + oh * 8 + o];

        float lmax = -1e30f;
        #pragma unroll
        for (int k = 0; k < NBLKS; ++k) {
            float dot = 0.f;
            #pragma unroll
            for (int o = 0; o < 8; ++o) dot = fmaf(P[k][o], ovr[o], dot);
            dot += __shfl_xor_sync(0xffffffffu, dot, 2);   // join o-halves
            const float L = (it == 1) ? dot : (Lr[k] + dot);
            Lr[k] = L;
            lmax = fmaxf(lmax, L);
        }
        #pragma unroll
        for (int off = 4; off <= 16; off <<= 1)
            lmax = fmaxf(lmax, __shfl_xor_sync(0xffffffffu, lmax, off));
        __syncthreads();
        if (lane < 2) sred[wid * 2 + g] = lmax;
        __syncthreads();
        float M = -1e30f;
        #pragma unroll
        for (int wi = 0; wi < NWARPS; ++wi)
            M = fmaxf(M, sred[wi * 2 + g]);

        float e[NBLKS], lsum = 0.f;
        #pragma unroll
        for (int k = 0; k < NBLKS; ++k) {
            e[k] = __expf(Lr[k] - M);
            lsum += e[k];
        }
        #pragma unroll
        for (int off = 4; off <= 16; off <<= 1)
            lsum += __shfl_xor_sync(0xffffffffu, lsum, off);
        __syncthreads();
        if (lane < 2) sred[wid * 2 + g] = lsum;
        __syncthreads();
        float Z = 0.f;
        #pragma unroll
        for (int wi = 0; wi < NWARPS; ++wi)
            Z += sred[wi * 2 + g];

        float acc[8];
        #pragma unroll
        for (int o = 0; o < 8; ++o) {
            float a = 0.f;
            #pragma unroll
            for (int k = 0; k < NBLKS; ++k) a = fmaf(e[k], P[k][o], a);
            acc[o] = a;
        }
        #pragma unroll
        for (int off = 4; off <= 16; off <<= 1)
            #pragma unroll
            for (int o = 0; o < 8; ++o)
                acc[o] += __shfl_xor_sync(0xffffffffu, acc[o], off);
        if (lane < 4) {
            #pragma unroll
            for (int o = 0; o < 8; ++o)
                wred[(wid * 2 + g) * 16 + oh * 8 + o] = acc[o];
        }
        __syncthreads();
        if (tid < 32) {
            const int g2 = tid & 1, o2 = tid >> 1;
            float sv = 0.f;
            #pragma unroll
            for (int wi = 0; wi < NWARPS; ++wi)
                sv += wred[(wi * 2 + g2) * 16 + o2];
            sv /= Z;
            float sq = sv * sv;
            #pragma unroll
            for (int off = 2; off <= 16; off <<= 1)
                sq += __shfl_xor_sync(0xffffffffu, sq, off);
            const float coef = sq / (1.f + sq) * rsqrtf(sq);
            outv[g2 * 16 + o2] = sv * coef;
        }
        __syncthreads();
    }

    // ================= output: [C, B, 1, 1, 16] =================
    if (tid < 32) {
        const int g2 = tid & 1, o2 = tid >> 1;
        out[((size_t)c * Bb + bbase + g2) * 16 + o2] = outv[g2 * 16 + o2];
    }
}

// ---------------- host ----------------
typedef CUresult (*EncodeTiledFn)(
    CUtensorMap*, CUtensorMapDataType, cuuint32_t, void*,
    const cuuint64_t*, const cuuint64_t*, const cuuint32_t*, const cuuint32_t*,
    CUtensorMapInterleave, CUtensorMapSwizzle, CUtensorMapL2promotion,
    CUtensorMapFloatOOBfill);

extern "C" void kernel_launch(void* const* d_in, const int* in_sizes, int n_in,
                              void* d_out, int out_size)
{
    const float* x = (const float*)d_in[0];
    void* w = (void*)d_in[1];
    float* out = (float*)d_out;

    // Build TMA descriptor: w viewed as 2D [128 floats x 11520 rows],
    // box [32 floats x 144 rows], SW128 swizzle.
    EncodeTiledFn encode = nullptr;
    cudaDriverEntryPointQueryResult qr;
    cudaGetDriverEntryPoint("cuTensorMapEncodeTiled", (void**)&encode,
                            cudaEnableDefault, &qr);

    CUtensorMap tmap;
    cuuint64_t dims[2]    = { 128, (cuuint64_t)Cc * Nn };
    cuuint64_t strides[1] = { 128 * 4 };
    cuuint32_t box[2]     = { 32, RPB };
    cuuint32_t estr[2]    = { 1, 1 };
    encode(&tmap, CU_TENSOR_MAP_DATA_TYPE_FLOAT32, 2, w,
           dims, strides, box, estr,
           CU_TENSOR_MAP_INTERLEAVE_NONE, CU_TENSOR_MAP_SWIZZLE_128B,
           CU_TENSOR_MAP_L2_PROMOTION_L2_128B,
           CU_TENSOR_MAP_FLOAT_OOB_FILL_NONE);

    cudaFuncSetAttribute(capsule_kernel,
                         cudaFuncAttributeMaxDynamicSharedMemorySize, SMEM_BYTES);

    const int grid = Cc * (Bb / 2);   // 1280 CTAs
    capsule_kernel<<<grid, NTHREADS, SMEM_BYTES>>>(tmap, x, out);
}